// round 8
// baseline (speedup 1.0000x reference)
#include <cuda_runtime.h>
#include <cstdint>

#define GENES 2048
#define HEADS 8
#define BATCH 16
#define NP 6           // Taylor powers 0..5 (|s|<~0.12 -> err < 2e-9)
#define TPB  256
#define NVAL 11        // A1..A5, B0..B5  (A0 = 2048 exact)
#define ARRIVALS (NVAL * HEADS)   // 88 remote arrivals per consumer mbarrier

__constant__ float c_invfact[NP] = {
    1.0f, 1.0f, 0.5f, 1.0f / 6.0f, 1.0f / 24.0f, 1.0f / 120.0f
};

// ---------------- packed f32x2 helpers ----------------
__device__ __forceinline__ unsigned long long pk2(float lo, float hi) {
    unsigned long long r;
    asm("mov.b64 %0, {%1, %2};" : "=l"(r) : "f"(lo), "f"(hi));
    return r;
}
__device__ __forceinline__ void upk2(float& lo, float& hi, unsigned long long v) {
    asm("mov.b64 {%0, %1}, %2;" : "=f"(lo), "=f"(hi) : "l"(v));
}
__device__ __forceinline__ unsigned long long mul2(unsigned long long a, unsigned long long b) {
    unsigned long long r;
    asm("mul.rn.f32x2 %0, %1, %2;" : "=l"(r) : "l"(a), "l"(b));
    return r;
}
__device__ __forceinline__ unsigned long long add2(unsigned long long a, unsigned long long b) {
    unsigned long long r;
    asm("add.rn.f32x2 %0, %1, %2;" : "=l"(r) : "l"(a), "l"(b));
    return r;
}
__device__ __forceinline__ unsigned long long fma2(unsigned long long a, unsigned long long b,
                                                   unsigned long long c) {
    unsigned long long r;
    asm("fma.rn.f32x2 %0, %1, %2, %3;" : "=l"(r) : "l"(a), "l"(b), "l"(c));
    return r;
}
__device__ __forceinline__ uint32_t smem_u32(const void* p) {
    uint32_t a;
    asm("{ .reg .u64 t; cvta.to.shared.u64 t, %1; cvt.u32.u64 %0, t; }" : "=r"(a) : "l"(p));
    return a;
}
// store value into rank's smem, then arrive (release, cluster) on rank's mbarrier
__device__ __forceinline__ void dsmem_store_arrive(uint32_t local_addr, uint32_t mbar_addr,
                                                   uint32_t rank, float val) {
    asm volatile(
        "{ .reg .b32 ra, rb;\n\t"
        "mapa.shared::cluster.u32 ra, %0, %2;\n\t"
        "st.shared::cluster.f32 [ra], %3;\n\t"
        "mapa.shared::cluster.u32 rb, %1, %2;\n\t"
        "mbarrier.arrive.release.cluster.shared::cluster.b64 _, [rb];\n\t}"
        :: "r"(local_addr), "r"(mbar_addr), "r"(rank), "f"(val) : "memory");
}

// ---------------------------------------------------------------------------
// One fused kernel. Cluster of 8 CTAs = one batch (rank = head), 256 threads.
// Timeline per CTA:
//   issue ALL global loads (phase-2 prefetch + phase-1 float4 tiles)
//   mbarrier.init(88) ; __syncthreads ; barrier.cluster arrive+wait
//        (the ~490cyc cluster wait overlaps the in-flight DRAM epoch)
//   phase-1 packed moment math ; pre-compute exp-diagonal terms (MUFU overlaps)
//   SHFL butterfly ; smem cross-warp stage
//   11 threads: st.shared::cluster + mbarrier.arrive.release.cluster to all 8 ranks
//   all threads: mbarrier.try_wait.parity.acquire.cluster  (~90cyc, not 490)
//   phase 2: packed head-pair Horner + divide, store output
// ---------------------------------------------------------------------------
__global__ void __launch_bounds__(TPB, 1) __cluster_dims__(HEADS, 1, 1)
fused_attn_kernel(const float* __restrict__ x,
                  const float* __restrict__ WQ,
                  const float* __restrict__ WK,
                  const float* __restrict__ WV,
                  const float* __restrict__ W0,
                  float* __restrict__ out)
{
    const int b   = blockIdx.x >> 3;
    const int h   = blockIdx.x & 7;
    const int tid = threadIdx.x;

    __shared__ __align__(8) unsigned long long mbar;     // consumer barrier
    __shared__ float sRed[8][NVAL];                      // per-warp partials
    __shared__ __align__(8) float sMomA[NP - 1][HEADS];  // A1..A5 per head
    __shared__ __align__(8) float sMomB[NP][HEADS];      // B0..B5 per head
    __shared__ float sW0[HEADS];

    const float* __restrict__ xb = x + b * GENES;

    // -------- Issue every global load now (one memory epoch) --------
    const int g = h * 256 + tid;
    const float xg = xb[g];
    float pq[HEADS], pkk[HEADS], pv[HEADS];
#pragma unroll
    for (int hh = 0; hh < HEADS; hh++) {
        pq[hh]  = WQ[hh * GENES + g];
        pkk[hh] = WK[hh * GENES + g];
        pv[hh]  = WV[hh * GENES + g];
    }
    if (tid < HEADS) sW0[tid] = W0[tid];

    const float4* __restrict__ x4  = (const float4*)xb;
    const float4* __restrict__ wk4 = (const float4*)(WK + h * GENES);
    const float4* __restrict__ wv4 = (const float4*)(WV + h * GENES);
    float4 xv[2], kv[2], vv[2];
#pragma unroll
    for (int e = 0; e < 2; e++) {            // 2 x float4 = 8 genes/thread
        const int i = tid + e * TPB;
        xv[e] = x4[i]; kv[e] = wk4[i]; vv[e] = wv4[i];
    }

    // -------- mbarrier init + one cluster sync, overlapped with DRAM --------
    const uint32_t mb = smem_u32(&mbar);
    if (tid == 0)
        asm volatile("mbarrier.init.shared.b64 [%0], %1;" :: "r"(mb), "r"((uint32_t)ARRIVALS) : "memory");
    __syncthreads();
    asm volatile("barrier.cluster.arrive.aligned;" ::: "memory");
    asm volatile("barrier.cluster.wait.aligned;"   ::: "memory");

    // -------- Phase 1: packed moments (2 gene-pairs per float4) --------
    unsigned long long A[NP - 1], Bm[NP];
#pragma unroll
    for (int n = 0; n < NP - 1; n++) A[n] = 0ull;
#pragma unroll
    for (int n = 0; n < NP; n++) Bm[n] = 0ull;

#pragma unroll
    for (int e = 0; e < 2; e++) {
        const unsigned long long xp0 = pk2(xv[e].x, xv[e].y);
        const unsigned long long xp1 = pk2(xv[e].z, xv[e].w);
        const unsigned long long k0  = mul2(xp0, pk2(kv[e].x, kv[e].y));
        const unsigned long long k1  = mul2(xp1, pk2(kv[e].z, kv[e].w));
        const unsigned long long v0  = mul2(xp0, pk2(vv[e].x, vv[e].y));
        const unsigned long long v1  = mul2(xp1, pk2(vv[e].z, vv[e].w));

        Bm[0] = add2(Bm[0], v0);
        Bm[0] = add2(Bm[0], v1);
        unsigned long long p0 = k0, p1 = k1;
#pragma unroll
        for (int n = 1; n < NP; n++) {
            A[n - 1] = add2(A[n - 1], p0);
            A[n - 1] = add2(A[n - 1], p1);
            Bm[n]    = fma2(p0, v0, Bm[n]);
            Bm[n]    = fma2(p1, v1, Bm[n]);
            if (n < NP - 1) { p0 = mul2(p0, k0); p1 = mul2(p1, k1); }
        }
    }

    // -------- Pre-barrier: exp-diagonal terms (MUFU overlaps SHFLs below) ---
    float qs[HEADS], ev[HEADS];
#pragma unroll
    for (int hh = 0; hh < HEADS; hh++) {
        qs[hh] = xg * pq[hh];
        ev[hh] = __expf(qs[hh] * (xg * pkk[hh])) * (xg * pv[hh]);
    }

    // -------- SHFL-butterfly warp reduce (11 scalars) --------
    float vals[NVAL];
#pragma unroll
    for (int n = 0; n < NP - 1; n++) {
        float lo, hi; upk2(lo, hi, A[n]);
        vals[n] = lo + hi;
    }
#pragma unroll
    for (int n = 0; n < NP; n++) {
        float lo, hi; upk2(lo, hi, Bm[n]);
        vals[NP - 1 + n] = lo + hi;
    }
#pragma unroll
    for (int i = 0; i < NVAL; i++) {
#pragma unroll
        for (int off = 16; off > 0; off >>= 1)
            vals[i] += __shfl_xor_sync(0xFFFFFFFFu, vals[i], off);
    }

    const int w    = tid >> 5;
    const int lane = tid & 31;
    if (lane == 0) {
#pragma unroll
        for (int i = 0; i < NVAL; i++) sRed[w][i] = vals[i];
    }
    __syncthreads();

    // -------- 11 threads: final sum + fan out to all 8 CTAs + arrive --------
    if (tid < NVAL) {
        float s = 0.0f;
#pragma unroll
        for (int ww = 0; ww < 8; ww++) s += sRed[ww][tid];
        float scaled;
        uint32_t addr;
        if (tid < NP - 1) {                               // A_{tid+1}
            scaled = s * c_invfact[tid + 1];
            addr = smem_u32(&sMomA[tid][h]);
        } else {                                          // B_{tid-(NP-1)}
            scaled = s * c_invfact[tid - (NP - 1)];
            addr = smem_u32(&sMomB[tid - (NP - 1)][h]);
        }
#pragma unroll
        for (int r = 0; r < HEADS; r++)
            dsmem_store_arrive(addr, mb, (uint32_t)r, scaled);
    }

    // -------- Wait for all 88 arrivals (acquire, cluster scope) --------
    asm volatile(
        "{\n\t.reg .pred P;\n\t"
        "WAIT_%=:\n\t"
        "mbarrier.try_wait.parity.acquire.cluster.shared::cta.b64 P, [%0], 0, 0x989680;\n\t"
        "@!P bra WAIT_%=;\n\t}"
        :: "r"(mb) : "memory");

    // -------- Phase 2: packed head-pair Horner --------
    const unsigned long long a0_2 = pk2(2048.0f, 2048.0f);   // A0/0! exact
    float acc = 0.0f;

#pragma unroll
    for (int p = 0; p < HEADS / 2; p++) {
        const int h0 = 2 * p, h1 = 2 * p + 1;
        const unsigned long long q2 = pk2(qs[h0], qs[h1]);

        unsigned long long P0 = *(const unsigned long long*)&sMomA[NP - 2][h0];
#pragma unroll
        for (int n = NP - 3; n >= 0; n--)
            P0 = fma2(P0, q2, *(const unsigned long long*)&sMomA[n][h0]);
        P0 = fma2(P0, q2, a0_2);

        unsigned long long P1 = *(const unsigned long long*)&sMomB[NP - 1][h0];
#pragma unroll
        for (int n = NP - 2; n >= 0; n--)
            P1 = fma2(P1, q2, *(const unsigned long long*)&sMomB[n][h0]);

        float P0a, P0b, P1a, P1b;
        upk2(P0a, P0b, P0);
        upk2(P1a, P1b, P1);

        const float z0 = __fdividef(P1a - ev[h0], P0a);
        const float z1 = __fdividef(P1b - ev[h1], P0b);
        acc = fmaf(z0, sW0[h0], acc);
        acc = fmaf(z1, sW0[h1], acc);
    }

    out[b * GENES + g] = acc;
}

// ---------------------------------------------------------------------------
extern "C" void kernel_launch(void* const* d_in, const int* in_sizes, int n_in,
                              void* d_out, int out_size)
{
    const float* x  = (const float*)d_in[0];
    const float* WQ = (const float*)d_in[1];
    const float* WK = (const float*)d_in[2];
    const float* WV = (const float*)d_in[3];
    const float* W0 = (const float*)d_in[4];
    float* out = (float*)d_out;

    fused_attn_kernel<<<BATCH * HEADS, TPB>>>(x, WQ, WK, WV, W0, out);
}

// round 9
// speedup vs baseline: 1.6106x; 1.6106x over previous
#include <cuda_runtime.h>
#include <cstdint>

#define GENES 2048
#define HEADS 8
#define BATCH 16
#define NP 6           // Taylor powers 0..5 (|s|<~0.12 -> err < 2e-9)
#define TPB  256
#define NVAL 11        // A1..A5, B0..B5  (A0 = 2048 exact)

__constant__ float c_invfact[NP] = {
    1.0f, 1.0f, 0.5f, 1.0f / 6.0f, 1.0f / 24.0f, 1.0f / 120.0f
};

// ---------------- packed f32x2 helpers ----------------
__device__ __forceinline__ unsigned long long pk2(float lo, float hi) {
    unsigned long long r;
    asm("mov.b64 %0, {%1, %2};" : "=l"(r) : "f"(lo), "f"(hi));
    return r;
}
__device__ __forceinline__ void upk2(float& lo, float& hi, unsigned long long v) {
    asm("mov.b64 {%0, %1}, %2;" : "=f"(lo), "=f"(hi) : "l"(v));
}
__device__ __forceinline__ unsigned long long mul2(unsigned long long a, unsigned long long b) {
    unsigned long long r;
    asm("mul.rn.f32x2 %0, %1, %2;" : "=l"(r) : "l"(a), "l"(b));
    return r;
}
__device__ __forceinline__ unsigned long long add2(unsigned long long a, unsigned long long b) {
    unsigned long long r;
    asm("add.rn.f32x2 %0, %1, %2;" : "=l"(r) : "l"(a), "l"(b));
    return r;
}
__device__ __forceinline__ unsigned long long fma2(unsigned long long a, unsigned long long b,
                                                   unsigned long long c) {
    unsigned long long r;
    asm("fma.rn.f32x2 %0, %1, %2, %3;" : "=l"(r) : "l"(a), "l"(b), "l"(c));
    return r;
}
__device__ __forceinline__ uint32_t smem_u32(const void* p) {
    uint32_t a;
    asm("{ .reg .u64 t; cvta.to.shared.u64 t, %1; cvt.u32.u64 %0, t; }" : "=r"(a) : "l"(p));
    return a;
}
__device__ __forceinline__ void dsmem_store(uint32_t local_addr, uint32_t rank, float val) {
    asm volatile(
        "{ .reg .b32 r; mapa.shared::cluster.u32 r, %0, %1; st.shared::cluster.f32 [r], %2; }"
        :: "r"(local_addr), "r"(rank), "f"(val) : "memory");
}

// ---------------------------------------------------------------------------
// One fused kernel. Cluster of 8 CTAs = one batch (rank = head), 256 threads.
// ROUND-7 STRUCTURE (best: 5.98us) + two cherry-picks from round 8:
//   * all phase-1 tiles loaded as float4 into registers at kernel entry
//   * exp-diagonal terms computed BEFORE the reduction (MUFU overlaps SHFLs)
// Phase 1 (packed f32x2): A_n = sum K^n (n=1..5), B_n = sum K^n V (n=0..5).
// SHFL butterfly -> smem cross-warp stage -> 11 threads fan the scaled moments
// out to ALL 8 cluster CTAs' smem via st.shared::cluster.
// barrier.cluster (arrive=release / wait=acquire) publishes them.
// Phase 2: packed head-pair Horner + exact-exp diagonal fixup + W0 combine.
// ---------------------------------------------------------------------------
__global__ void __launch_bounds__(TPB, 1) __cluster_dims__(HEADS, 1, 1)
fused_attn_kernel(const float* __restrict__ x,
                  const float* __restrict__ WQ,
                  const float* __restrict__ WK,
                  const float* __restrict__ WV,
                  const float* __restrict__ W0,
                  float* __restrict__ out)
{
    const int b   = blockIdx.x >> 3;
    const int h   = blockIdx.x & 7;
    const int tid = threadIdx.x;

    __shared__ float sRed[8][NVAL];                       // per-warp partials
    __shared__ __align__(8) float sMomA[NP - 1][HEADS];   // A1..A5 per head
    __shared__ __align__(8) float sMomB[NP][HEADS];       // B0..B5 per head
    __shared__ float sW0[HEADS];

    const float* __restrict__ xb = x + b * GENES;

    // -------- Issue every global load up front (one memory epoch) --------
    const int g = h * 256 + tid;
    const float xg = xb[g];
    float pq[HEADS], pkk[HEADS], pv[HEADS];
#pragma unroll
    for (int hh = 0; hh < HEADS; hh++) {
        pq[hh]  = WQ[hh * GENES + g];
        pkk[hh] = WK[hh * GENES + g];
        pv[hh]  = WV[hh * GENES + g];
    }
    if (tid < HEADS) sW0[tid] = W0[tid];

    const float4* __restrict__ x4  = (const float4*)xb;
    const float4* __restrict__ wk4 = (const float4*)(WK + h * GENES);
    const float4* __restrict__ wv4 = (const float4*)(WV + h * GENES);
    float4 xv[2], kv[2], vv[2];
#pragma unroll
    for (int e = 0; e < 2; e++) {            // 2 x float4 = 8 genes/thread
        const int i = tid + e * TPB;
        xv[e] = x4[i]; kv[e] = wk4[i]; vv[e] = wv4[i];
    }

    // -------- Phase 1: packed moments (2 gene-pairs per float4) --------
    unsigned long long A[NP - 1], Bm[NP];
#pragma unroll
    for (int n = 0; n < NP - 1; n++) A[n] = 0ull;
#pragma unroll
    for (int n = 0; n < NP; n++) Bm[n] = 0ull;

#pragma unroll
    for (int e = 0; e < 2; e++) {
        const unsigned long long xp0 = pk2(xv[e].x, xv[e].y);
        const unsigned long long xp1 = pk2(xv[e].z, xv[e].w);
        const unsigned long long k0  = mul2(xp0, pk2(kv[e].x, kv[e].y));
        const unsigned long long k1  = mul2(xp1, pk2(kv[e].z, kv[e].w));
        const unsigned long long v0  = mul2(xp0, pk2(vv[e].x, vv[e].y));
        const unsigned long long v1  = mul2(xp1, pk2(vv[e].z, vv[e].w));

        Bm[0] = add2(Bm[0], v0);
        Bm[0] = add2(Bm[0], v1);
        unsigned long long p0 = k0, p1 = k1;
#pragma unroll
        for (int n = 1; n < NP; n++) {
            A[n - 1] = add2(A[n - 1], p0);
            A[n - 1] = add2(A[n - 1], p1);
            Bm[n]    = fma2(p0, v0, Bm[n]);
            Bm[n]    = fma2(p1, v1, Bm[n]);
            if (n < NP - 1) { p0 = mul2(p0, k0); p1 = mul2(p1, k1); }
        }
    }

    // -------- Exp-diagonal terms now: MUFU latency hides under SHFLs --------
    float qs[HEADS], ev[HEADS];
#pragma unroll
    for (int hh = 0; hh < HEADS; hh++) {
        qs[hh] = xg * pq[hh];
        ev[hh] = __expf(qs[hh] * (xg * pkk[hh])) * (xg * pv[hh]);
    }

    // -------- SHFL-butterfly warp reduce (11 scalars) --------
    float vals[NVAL];
#pragma unroll
    for (int n = 0; n < NP - 1; n++) {
        float lo, hi; upk2(lo, hi, A[n]);
        vals[n] = lo + hi;
    }
#pragma unroll
    for (int n = 0; n < NP; n++) {
        float lo, hi; upk2(lo, hi, Bm[n]);
        vals[NP - 1 + n] = lo + hi;
    }
#pragma unroll
    for (int i = 0; i < NVAL; i++) {
#pragma unroll
        for (int off = 16; off > 0; off >>= 1)
            vals[i] += __shfl_xor_sync(0xFFFFFFFFu, vals[i], off);
    }

    const int w    = tid >> 5;
    const int lane = tid & 31;
    if (lane == 0) {
#pragma unroll
        for (int i = 0; i < NVAL; i++) sRed[w][i] = vals[i];
    }
    __syncthreads();

    // -------- 11 threads: final sum, scale, DSMEM fan-out to all 8 CTAs -----
    if (tid < NVAL) {
        float s = 0.0f;
#pragma unroll
        for (int ww = 0; ww < 8; ww++) s += sRed[ww][tid];
        float scaled;
        uint32_t addr;
        if (tid < NP - 1) {                               // A_{tid+1}
            scaled = s * c_invfact[tid + 1];
            addr = smem_u32(&sMomA[tid][h]);
        } else {                                          // B_{tid-(NP-1)}
            scaled = s * c_invfact[tid - (NP - 1)];
            addr = smem_u32(&sMomB[tid - (NP - 1)][h]);
        }
#pragma unroll
        for (int r = 0; r < HEADS; r++) dsmem_store(addr, (uint32_t)r, scaled);
    }

    // -------- Cluster barrier: release our stores / acquire peers' ----------
    asm volatile("barrier.cluster.arrive.aligned;" ::: "memory");
    asm volatile("barrier.cluster.wait.aligned;"   ::: "memory");

    // -------- Phase 2: packed head-pair Horner (pure smem-broadcast math) ---
    const unsigned long long a0_2 = pk2(2048.0f, 2048.0f);   // A0/0! exact
    float acc = 0.0f;

#pragma unroll
    for (int p = 0; p < HEADS / 2; p++) {
        const int h0 = 2 * p, h1 = 2 * p + 1;
        const unsigned long long q2 = pk2(qs[h0], qs[h1]);

        unsigned long long P0 = *(const unsigned long long*)&sMomA[NP - 2][h0];
#pragma unroll
        for (int n = NP - 3; n >= 0; n--)
            P0 = fma2(P0, q2, *(const unsigned long long*)&sMomA[n][h0]);
        P0 = fma2(P0, q2, a0_2);

        unsigned long long P1 = *(const unsigned long long*)&sMomB[NP - 1][h0];
#pragma unroll
        for (int n = NP - 2; n >= 0; n--)
            P1 = fma2(P1, q2, *(const unsigned long long*)&sMomB[n][h0]);

        float P0a, P0b, P1a, P1b;
        upk2(P0a, P0b, P0);
        upk2(P1a, P1b, P1);

        const float z0 = __fdividef(P1a - ev[h0], P0a);
        const float z1 = __fdividef(P1b - ev[h1], P0b);
        acc = fmaf(z0, sW0[h0], acc);
        acc = fmaf(z1, sW0[h1], acc);
    }

    out[b * GENES + g] = acc;
}

// ---------------------------------------------------------------------------
extern "C" void kernel_launch(void* const* d_in, const int* in_sizes, int n_in,
                              void* d_out, int out_size)
{
    const float* x  = (const float*)d_in[0];
    const float* WQ = (const float*)d_in[1];
    const float* WK = (const float*)d_in[2];
    const float* WV = (const float*)d_in[3];
    const float* W0 = (const float*)d_in[4];
    float* out = (float*)d_out;

    fused_attn_kernel<<<BATCH * HEADS, TPB>>>(x, WQ, WK, WV, W0, out);
}